// round 6
// baseline (speedup 1.0000x reference)
#include <cuda_runtime.h>
#include <cuda_bf16.h>
#include <stdint.h>
#include <math.h>

#define BB 2
#define LL 192
#define DD 384
#define HH 8
#define DHH 48
#define NN 384
#define EPSF 1e-5f

// Scratch (allocation-free rule: __device__ globals)
__device__ float g_xn[BB * LL * DD];          // layernormed x (fp32, for v-proj)
__device__ __nv_bfloat16 g_xh[BB * LL * DD];  // xn split-bf16 hi
__device__ __nv_bfloat16 g_xl[BB * LL * DD];  // xn split-bf16 lo
__device__ float g_v[BB * LL * NN];           // v projection
__device__ float g_dots[BB * HH * LL * LL];   // attention logits -> probs (in place)
__device__ float g_ao[BB * LL * NN];          // attn @ v, head-merged
// Pre-split, pre-transposed weights: [r][n=384][k=384] bf16 (ldmatrix-B ready)
__device__ __nv_bfloat16 g_wqh[LL * NN * DD];
__device__ __nv_bfloat16 g_wql[LL * NN * DD];
__device__ __nv_bfloat16 g_wkh[LL * NN * DD];
__device__ __nv_bfloat16 g_wkl[LL * NN * DD];

// ======================= baseline-PTX tensor helpers (sm_80+) =======================
__device__ __forceinline__ uint32_t smem_u32(const void* p) {
    uint32_t a;
    asm("{ .reg .u64 t; cvta.to.shared.u64 t, %1; cvt.u32.u64 %0, t; }" : "=r"(a) : "l"(p));
    return a;
}
__device__ __forceinline__ void ldsm4(uint32_t addr, uint32_t& r0, uint32_t& r1, uint32_t& r2,
                                      uint32_t& r3) {
    asm volatile("ldmatrix.sync.aligned.m8n8.x4.shared.b16 {%0,%1,%2,%3}, [%4];"
                 : "=r"(r0), "=r"(r1), "=r"(r2), "=r"(r3)
                 : "r"(addr));
}
__device__ __forceinline__ void mma_bf16(float* c, uint32_t a0, uint32_t a1, uint32_t a2,
                                         uint32_t a3, uint32_t b0, uint32_t b1) {
    asm volatile(
        "mma.sync.aligned.m16n8k16.row.col.f32.bf16.bf16.f32 "
        "{%0,%1,%2,%3}, {%4,%5,%6,%7}, {%8,%9}, {%0,%1,%2,%3};"
        : "+f"(c[0]), "+f"(c[1]), "+f"(c[2]), "+f"(c[3])
        : "r"(a0), "r"(a1), "r"(a2), "r"(a3), "r"(b0), "r"(b1));
}
__device__ __forceinline__ void cp16(uint32_t dst, const void* src, int src_bytes) {
    asm volatile("cp.async.cg.shared.global [%0], [%1], 16, %2;" ::"r"(dst), "l"(src),
                 "r"(src_bytes)
                 : "memory");
}
__device__ __forceinline__ void cp_wait_all() {
    asm volatile("cp.async.wait_all;" ::: "memory");
}

// ======================= weight pre-split + transpose =======================
// u[r][k][n] fp32 -> (hi,lo)[r][n][k] bf16. One 64x64 tile per block.
__global__ void __launch_bounds__(256) wprep_kernel(const float* __restrict__ u, int which) {
    __shared__ float s[64][65];
    const int r = blockIdx.z;
    const int k0 = blockIdx.x * 64, n0 = blockIdx.y * 64;
    const int tid = threadIdx.x;
    const float* src = u + ((size_t)r * DD + k0) * NN + n0;
    for (int idx = tid; idx < 4096; idx += 256) {
        const int i = idx >> 6, j = idx & 63;
        s[i][j] = src[(size_t)i * NN + j];
    }
    __syncthreads();
    __nv_bfloat16* hA = which ? g_wkh : g_wqh;
    __nv_bfloat16* lA = which ? g_wkl : g_wql;
    for (int idx = tid; idx < 2048; idx += 256) {
        const int j = idx >> 5, i2 = (idx & 31) * 2;
        const float v0 = s[i2][j], v1 = s[i2 + 1][j];
        __nv_bfloat162 hi, lo;
        hi.x = __float2bfloat16(v0);
        hi.y = __float2bfloat16(v1);
        lo.x = __float2bfloat16(v0 - __bfloat162float(hi.x));
        lo.y = __float2bfloat16(v1 - __bfloat162float(hi.y));
        const size_t o = ((size_t)r * NN + n0 + j) * DD + k0 + i2;
        *(uint32_t*)((char*)hA + o * 2) = *(uint32_t*)&hi;
        *(uint32_t*)((char*)lA + o * 2) = *(uint32_t*)&lo;
    }
}

// ======================= LayerNorm (+ split-bf16 precompute) =======================
__global__ void __launch_bounds__(128) ln_kernel(const float* __restrict__ x,
                                                 const float* __restrict__ gamma,
                                                 const float* __restrict__ beta) {
    const int row = blockIdx.x;
    const int tid = threadIdx.x;
    const float* xr = x + (size_t)row * DD;
    float s = 0.f, s2 = 0.f;
    for (int c = tid; c < DD; c += 128) {
        float t = xr[c];
        s += t;
        s2 += t * t;
    }
    for (int o = 16; o; o >>= 1) {
        s += __shfl_xor_sync(0xffffffffu, s, o);
        s2 += __shfl_xor_sync(0xffffffffu, s2, o);
    }
    __shared__ float sh[8];
    const int w = tid >> 5;
    if ((tid & 31) == 0) {
        sh[w] = s;
        sh[4 + w] = s2;
    }
    __syncthreads();
    s = sh[0] + sh[1] + sh[2] + sh[3];
    s2 = sh[4] + sh[5] + sh[6] + sh[7];
    const float mu = s * (1.0f / DD);
    const float var = s2 * (1.0f / DD) - mu * mu;
    const float rstd = rsqrtf(var + EPSF);
    for (int c = tid; c < DD; c += 128) {
        const float v = (xr[c] - mu) * rstd * gamma[c] + beta[c];
        g_xn[(size_t)row * DD + c] = v;
        const __nv_bfloat16 hi = __float2bfloat16(v);
        g_xh[(size_t)row * DD + c] = hi;
        g_xl[(size_t)row * DD + c] = __float2bfloat16(v - __bfloat162float(hi));
    }
}

// ======================= small fp32 GEMM (v / o projections) =======================
__device__ __forceinline__ void gemm384_body(const float* __restrict__ A,
                                             const float* __restrict__ Bw,
                                             const float* __restrict__ bias,
                                             float* __restrict__ C, bool has_bias) {
    __shared__ __align__(16) float As[16][68];
    __shared__ __align__(16) float Bs[16][68];
    const int bm = blockIdx.y * 64, bn = blockIdx.x * 64;
    const int tid = threadIdx.x;
    const int tx = tid & 15, ty = tid >> 4;
    float acc[4][4] = {};
    for (int k0 = 0; k0 < 384; k0 += 16) {
        for (int idx = tid; idx < 64 * 16; idx += 256) {
            int m = idx >> 4, kk = idx & 15;
            As[kk][m] = A[(size_t)(bm + m) * 384 + k0 + kk];
        }
        for (int idx = tid; idx < 16 * 64; idx += 256) {
            int kk = idx >> 6, n = idx & 63;
            Bs[kk][n] = Bw[(size_t)(k0 + kk) * 384 + bn + n];
        }
        __syncthreads();
#pragma unroll
        for (int kk = 0; kk < 16; ++kk) {
            float4 av = *(const float4*)&As[kk][ty * 4];
            float4 bv = *(const float4*)&Bs[kk][tx * 4];
            float a[4] = {av.x, av.y, av.z, av.w};
            float b[4] = {bv.x, bv.y, bv.z, bv.w};
#pragma unroll
            for (int i = 0; i < 4; ++i)
#pragma unroll
                for (int j = 0; j < 4; ++j) acc[i][j] += a[i] * b[j];
        }
        __syncthreads();
    }
#pragma unroll
    for (int i = 0; i < 4; ++i)
#pragma unroll
        for (int j = 0; j < 4; ++j) {
            int row = bm + ty * 4 + i, col = bn + tx * 4 + j;
            float o = acc[i][j];
            if (has_bias) o += bias[col];
            C[(size_t)row * 384 + col] = o;
        }
}
__global__ void __launch_bounds__(256) vproj_kernel(const float* __restrict__ wv) {
    gemm384_body(g_xn, wv, nullptr, g_v, false);
}
__global__ void __launch_bounds__(256) oproj_kernel(const float* __restrict__ wo,
                                                    const float* __restrict__ bo,
                                                    float* __restrict__ out) {
    gemm384_body(g_ao, wo, bo, out, true);
}

// ======================= dots via mma.sync HMMA (split-bf16, 3 products) =======================
#define MT 128
#define KC 64
#define ASTRIDE 144
#define A_BUF 73728   // 4 arrays (QH,QL,KH,KL) of 128*144
#define W_BUF 27648   // 4 arrays of 48*144
#define W_BASE 147456
#define SM_TOTAL (W_BASE + 2 * W_BUF)  // 202752 bytes

#define AQH 0
#define AQL 18432
#define AKH 36864
#define AKL 55296
#define WQH 0
#define WQL 6912
#define WKH 13824
#define WKL 20736

__device__ __forceinline__ void stage_A(uint32_t abase, int m0, int nbr, int tot, int r, int k0,
                                        int tid) {
    const char* xh = (const char*)g_xh;
    const char* xl = (const char*)g_xl;
#pragma unroll
    for (int q = tid; q < 128 * 8; q += 256) {
        const int m = q >> 3, seg = q & 7;
        const int u = m0 + m;
        const int valid = (u < tot) ? 16 : 0;
        int b = (u >= nbr) ? 1 : 0;
        int t = u - b * nbr;
        if (!valid) {
            b = 0;
            t = 0;
        }
        const int rowq = b * LL + r + t;
        const int rowk = b * LL + t;
        const size_t boff = (size_t)k0 * 2 + seg * 16;
        const uint32_t so = abase + m * ASTRIDE + seg * 16;
        cp16(so + AQH, xh + (size_t)rowq * (DD * 2) + boff, valid);
        cp16(so + AQL, xl + (size_t)rowq * (DD * 2) + boff, valid);
        cp16(so + AKH, xh + (size_t)rowk * (DD * 2) + boff, valid);
        cp16(so + AKL, xl + (size_t)rowk * (DD * 2) + boff, valid);
    }
}

// Pure-copy W staging from pre-split [r][n][k] bf16 arrays.
__device__ __forceinline__ void stage_W(uint32_t wbase, int rq, int rk, int n0, int k0, int tid) {
    const char* qh = (const char*)g_wqh;
    const char* ql = (const char*)g_wql;
    const char* kh = (const char*)g_wkh;
    const char* kl = (const char*)g_wkl;
#pragma unroll
    for (int q = tid; q < 48 * 8; q += 256) {
        const int row = q >> 3, seg = q & 7;
        const size_t offq = (((size_t)rq * NN + n0 + row) * DD + k0) * 2 + seg * 16;
        const size_t offk = (((size_t)rk * NN + n0 + row) * DD + k0) * 2 + seg * 16;
        const uint32_t so = wbase + row * ASTRIDE + seg * 16;
        cp16(so + WQH, qh + offq, 16);
        cp16(so + WQL, ql + offq, 16);
        cp16(so + WKH, kh + offk, 16);
        cp16(so + WKL, kl + offk, 16);
    }
}

__global__ void __launch_bounds__(256) dots_mma_kernel() {
    const int r = blockIdx.y;
    const int m0 = blockIdx.x * MT;
    const int nbr = LL - r;
    const int tot = 2 * nbr;
    if (m0 >= tot) return;

    extern __shared__ char smem[];
    const uint32_t sb = smem_u32(smem);
    const int tid = threadIdx.x;
    const int wid = tid >> 5, lane = tid & 31;
    const int rq = LL - 1 - r, rk = r;

    // prologue: stage (h=0, kc=0) into buffer 0
    stage_A(sb, m0, nbr, tot, r, 0, tid);
    stage_W(sb + W_BASE, rq, rk, 0, 0, tid);
    cp_wait_all();
    __syncthreads();

    const float scale = 0.14433756729740643f; // 48^-0.5
    const int wm0 = wid * 16;
    const int a_row = wm0 + (lane & 15);
    const int a_cadd = ((lane >> 4) << 3);
    const int b_radd = ((lane >> 4) & 1) * 8 + (lane & 7);
    const int b_cadd = ((lane >> 3) & 1) * 8;

    int it = 0;
    for (int h = 0; h < HH; ++h) {
        float accQ[6][4] = {};
        float accK[6][4] = {};
        for (int kc = 0; kc < 6; ++kc, ++it) {
            const int buf = it & 1;
            const uint32_t aB = sb + buf * A_BUF;
            const uint32_t wB = sb + W_BASE + buf * W_BUF;

            // prefetch next chunk into other buffer
            const int nit = it + 1;
            if (nit < 48) {
                const int nh = nit / 6, nkc = nit - nh * 6;
                stage_A(sb + (nit & 1) * A_BUF, m0, nbr, tot, r, nkc * KC, tid);
                stage_W(sb + W_BASE + (nit & 1) * W_BUF, rq, rk, nh * DHH, nkc * KC, tid);
            }

            // ---- MMA on current buffer ----
#pragma unroll
            for (int ks = 0; ks < 4; ++ks) {
                const uint32_t aoff = aB + a_row * ASTRIDE + (ks * 16 + a_cadd) * 2;
                uint32_t qh0, qh1, qh2, qh3, ql0, ql1, ql2, ql3;
                uint32_t kh0, kh1, kh2, kh3, kl0, kl1, kl2, kl3;
                ldsm4(aoff + AQH, qh0, qh1, qh2, qh3);
                ldsm4(aoff + AQL, ql0, ql1, ql2, ql3);
                ldsm4(aoff + AKH, kh0, kh1, kh2, kh3);
                ldsm4(aoff + AKL, kl0, kl1, kl2, kl3);
#pragma unroll
                for (int ntp = 0; ntp < 3; ++ntp) {
                    const uint32_t boff =
                        wB + (ntp * 16 + b_radd) * ASTRIDE + (ks * 16 + b_cadd) * 2;
                    uint32_t wq0, wq1, wq2, wq3, wl0, wl1, wl2, wl3;
                    uint32_t vk0, vk1, vk2, vk3, vl0, vl1, vl2, vl3;
                    ldsm4(boff + WQH, wq0, wq1, wq2, wq3);
                    ldsm4(boff + WQL, wl0, wl1, wl2, wl3);
                    ldsm4(boff + WKH, vk0, vk1, vk2, vk3);
                    ldsm4(boff + WKL, vl0, vl1, vl2, vl3);
                    mma_bf16(accQ[2 * ntp], qh0, qh1, qh2, qh3, wq0, wq1);
                    mma_bf16(accQ[2 * ntp], qh0, qh1, qh2, qh3, wl0, wl1);
                    mma_bf16(accQ[2 * ntp], ql0, ql1, ql2, ql3, wq0, wq1);
                    mma_bf16(accQ[2 * ntp + 1], qh0, qh1, qh2, qh3, wq2, wq3);
                    mma_bf16(accQ[2 * ntp + 1], qh0, qh1, qh2, qh3, wl2, wl3);
                    mma_bf16(accQ[2 * ntp + 1], ql0, ql1, ql2, ql3, wq2, wq3);
                    mma_bf16(accK[2 * ntp], kh0, kh1, kh2, kh3, vk0, vk1);
                    mma_bf16(accK[2 * ntp], kh0, kh1, kh2, kh3, vl0, vl1);
                    mma_bf16(accK[2 * ntp], kl0, kl1, kl2, kl3, vk0, vk1);
                    mma_bf16(accK[2 * ntp + 1], kh0, kh1, kh2, kh3, vk2, vk3);
                    mma_bf16(accK[2 * ntp + 1], kh0, kh1, kh2, kh3, vl2, vl3);
                    mma_bf16(accK[2 * ntp + 1], kl0, kl1, kl2, kl3, vk2, vk3);
                }
            }

            // ---- epilogue at end of head: diagonal pairing + row sums ----
            if (kc == 5) {
                float sl = 0.f, sh2 = 0.f;
#pragma unroll
                for (int nt = 0; nt < 6; ++nt) {
                    sl += accQ[nt][0] * accK[nt][0] + accQ[nt][1] * accK[nt][1];
                    sh2 += accQ[nt][2] * accK[nt][2] + accQ[nt][3] * accK[nt][3];
                }
                sl += __shfl_xor_sync(0xffffffffu, sl, 1);
                sl += __shfl_xor_sync(0xffffffffu, sl, 2);
                sh2 += __shfl_xor_sync(0xffffffffu, sh2, 1);
                sh2 += __shfl_xor_sync(0xffffffffu, sh2, 2);
                if ((lane & 3) == 0) {
                    const int ur = m0 + wm0 + (lane >> 2);
#pragma unroll
                    for (int half = 0; half < 2; ++half) {
                        const int u = ur + half * 8;
                        const float s = half ? sh2 : sl;
                        if (u < tot) {
                            const int b = (u >= nbr);
                            const int t = u - b * nbr;
                            const int ig = r + t;
                            g_dots[(((size_t)b * HH + h) * LL + ig) * LL + t] = s * scale;
                        }
                    }
                }
            }

            cp_wait_all();
            __syncthreads();
        }
    }
}

// ======================= causal softmax =======================
__global__ void __launch_bounds__(128) softmax_kernel() {
    const int row = blockIdx.x * 4 + (threadIdx.x >> 5);
    if (row >= BB * HH * LL) return;
    const int lane = threadIdx.x & 31;
    const int i = row % LL;
    float* d = g_dots + (size_t)row * LL;
    const int n = i + 1;
    float mx = -1e30f;
    for (int j = lane; j < n; j += 32) mx = fmaxf(mx, d[j]);
    for (int o = 16; o; o >>= 1) mx = fmaxf(mx, __shfl_xor_sync(0xffffffffu, mx, o));
    float s = 0.f;
    for (int j = lane; j < n; j += 32) {
        float e = __expf(d[j] - mx);
        d[j] = e;
        s += e;
    }
    for (int o = 16; o; o >>= 1) s += __shfl_xor_sync(0xffffffffu, s, o);
    const float inv = 1.f / s;
    for (int j = lane; j < n; j += 32) d[j] *= inv;
}

// ======================= attn @ v =======================
__global__ void __launch_bounds__(192) av_kernel() {
    const int local = threadIdx.x / DHH;
    const int dd = threadIdx.x % DHH;
    const int task = blockIdx.x * 4 + local;
    if (task >= BB * HH * LL) return;
    const int i = task % LL;
    const int bh = task / LL;
    const int h = bh % HH;
    const int b = bh / HH;
    const float* attn = g_dots + (size_t)task * LL;
    const float* vp = g_v + (size_t)b * LL * NN + h * DHH + dd;
    float acc = 0.f;
    for (int j = 0; j <= i; ++j) acc += attn[j] * vp[(size_t)j * NN];
    g_ao[((size_t)b * LL + i) * NN + h * DHH + dd] = acc;
}

// ======================= launcher =======================
extern "C" void kernel_launch(void* const* d_in, const int* in_sizes, int n_in,
                              void* d_out, int out_size) {
    const float* x = (const float*)d_in[0];
    const float* gamma = (const float*)d_in[1];
    const float* beta = (const float*)d_in[2];
    const float* uq = (const float*)d_in[3];
    const float* uk = (const float*)d_in[4];
    const float* wv = (const float*)d_in[5];
    const float* wo = (const float*)d_in[6];
    const float* bo = (const float*)d_in[7];
    float* out = (float*)d_out;

    cudaFuncSetAttribute(dots_mma_kernel, cudaFuncAttributeMaxDynamicSharedMemorySize, SM_TOTAL);

    wprep_kernel<<<dim3(6, 6, LL), 256>>>(uq, 0);
    wprep_kernel<<<dim3(6, 6, LL), 256>>>(uk, 1);
    ln_kernel<<<BB * LL, 128>>>(x, gamma, beta);
    vproj_kernel<<<dim3(6, 6), 256>>>(wv);
    dots_mma_kernel<<<dim3(3, LL), 256, SM_TOTAL>>>();
    softmax_kernel<<<(BB * HH * LL + 3) / 4, 128>>>();
    av_kernel<<<(BB * HH * LL + 3) / 4, 192>>>();
    oproj_kernel<<<dim3(6, 6), 256>>>(wo, bo, out);
}

// round 8
// speedup vs baseline: 1.4201x; 1.4201x over previous
#include <cuda_runtime.h>
#include <cuda_bf16.h>
#include <stdint.h>
#include <math.h>

#define BB 2
#define LL 192
#define DD 384
#define HH 8
#define DHH 48
#define NN 384
#define EPSF 1e-5f

// Scratch (allocation-free rule: __device__ globals)
__device__ float g_xn[BB * LL * DD];          // layernormed x (fp32, for v-proj)
__device__ __nv_bfloat16 g_xh[BB * LL * DD];  // xn split-bf16 hi
__device__ __nv_bfloat16 g_xl[BB * LL * DD];  // xn split-bf16 lo
__device__ float g_v[BB * LL * NN];           // v projection
__device__ float g_dots[BB * HH * LL * LL];   // attention logits -> probs (in place)
__device__ float g_ao[BB * LL * NN];          // attn @ v, head-merged

// ======================= baseline-PTX tensor helpers (sm_80+) =======================
__device__ __forceinline__ uint32_t smem_u32(const void* p) {
    uint32_t a;
    asm("{ .reg .u64 t; cvta.to.shared.u64 t, %1; cvt.u32.u64 %0, t; }" : "=r"(a) : "l"(p));
    return a;
}
__device__ __forceinline__ void ldsm4(uint32_t addr, uint32_t& r0, uint32_t& r1, uint32_t& r2,
                                      uint32_t& r3) {
    asm volatile("ldmatrix.sync.aligned.m8n8.x4.shared.b16 {%0,%1,%2,%3}, [%4];"
                 : "=r"(r0), "=r"(r1), "=r"(r2), "=r"(r3)
                 : "r"(addr));
}
__device__ __forceinline__ void mma_bf16(float* c, uint32_t a0, uint32_t a1, uint32_t a2,
                                         uint32_t a3, uint32_t b0, uint32_t b1) {
    asm volatile(
        "mma.sync.aligned.m16n8k16.row.col.f32.bf16.bf16.f32 "
        "{%0,%1,%2,%3}, {%4,%5,%6,%7}, {%8,%9}, {%0,%1,%2,%3};"
        : "+f"(c[0]), "+f"(c[1]), "+f"(c[2]), "+f"(c[3])
        : "r"(a0), "r"(a1), "r"(a2), "r"(a3), "r"(b0), "r"(b1));
}
__device__ __forceinline__ void cp16(uint32_t dst, const void* src, int src_bytes) {
    asm volatile("cp.async.cg.shared.global [%0], [%1], 16, %2;" ::"r"(dst), "l"(src),
                 "r"(src_bytes)
                 : "memory");
}
__device__ __forceinline__ void cp_wait_all() {
    asm volatile("cp.async.wait_all;" ::: "memory");
}

// ======================= LayerNorm (+ split-bf16 precompute) =======================
__global__ void __launch_bounds__(128) ln_kernel(const float* __restrict__ x,
                                                 const float* __restrict__ gamma,
                                                 const float* __restrict__ beta) {
    const int row = blockIdx.x;
    const int tid = threadIdx.x;
    const float* xr = x + (size_t)row * DD;
    float s = 0.f, s2 = 0.f;
    for (int c = tid; c < DD; c += 128) {
        float t = xr[c];
        s += t;
        s2 += t * t;
    }
    for (int o = 16; o; o >>= 1) {
        s += __shfl_xor_sync(0xffffffffu, s, o);
        s2 += __shfl_xor_sync(0xffffffffu, s2, o);
    }
    __shared__ float sh[8];
    const int w = tid >> 5;
    if ((tid & 31) == 0) {
        sh[w] = s;
        sh[4 + w] = s2;
    }
    __syncthreads();
    s = sh[0] + sh[1] + sh[2] + sh[3];
    s2 = sh[4] + sh[5] + sh[6] + sh[7];
    const float mu = s * (1.0f / DD);
    const float var = s2 * (1.0f / DD) - mu * mu;
    const float rstd = rsqrtf(var + EPSF);
    for (int c = tid; c < DD; c += 128) {
        const float v = (xr[c] - mu) * rstd * gamma[c] + beta[c];
        g_xn[(size_t)row * DD + c] = v;
        const __nv_bfloat16 hi = __float2bfloat16(v);
        g_xh[(size_t)row * DD + c] = hi;
        g_xl[(size_t)row * DD + c] = __float2bfloat16(v - __bfloat162float(hi));
    }
}

// ======================= small fp32 GEMM, 32x32 tiles (v / o projections) =======================
__global__ void __launch_bounds__(128) gemm32_kernel(const float* __restrict__ A,
                                                     const float* __restrict__ Bw,
                                                     const float* __restrict__ bias,
                                                     float* __restrict__ C, int has_bias) {
    __shared__ float As[32][33];
    __shared__ float Bs[32][36];
    const int bm = blockIdx.y * 32, bn = blockIdx.x * 32;
    const int tid = threadIdx.x;
    const int tx = tid & 7, ty = tid >> 3;  // 8 x 4 cols, 16 x 2 rows
    float acc[2][4] = {};
    for (int k0 = 0; k0 < 384; k0 += 32) {
#pragma unroll
        for (int idx = tid; idx < 1024; idx += 128) {
            const int m = idx >> 5, kk = idx & 31;
            As[kk][m] = A[(size_t)(bm + m) * 384 + k0 + kk];
        }
#pragma unroll
        for (int idx = tid; idx < 1024; idx += 128) {
            const int kk = idx >> 5, n = idx & 31;
            Bs[kk][n] = Bw[(size_t)(k0 + kk) * 384 + bn + n];
        }
        __syncthreads();
#pragma unroll
        for (int kk = 0; kk < 32; ++kk) {
            const float a0 = As[kk][ty * 2], a1 = As[kk][ty * 2 + 1];
            const float4 b4 = *(const float4*)&Bs[kk][tx * 4];
            const float b[4] = {b4.x, b4.y, b4.z, b4.w};
#pragma unroll
            for (int j = 0; j < 4; ++j) {
                acc[0][j] += a0 * b[j];
                acc[1][j] += a1 * b[j];
            }
        }
        __syncthreads();
    }
#pragma unroll
    for (int i = 0; i < 2; ++i)
#pragma unroll
        for (int j = 0; j < 4; ++j) {
            const int row = bm + ty * 2 + i, col = bn + tx * 4 + j;
            float o = acc[i][j];
            if (has_bias) o += bias[col];
            C[(size_t)row * 384 + col] = o;
        }
}

// ======================= dots via mma.sync HMMA (split-bf16, 3 products) =======================
// CTA = (r = blockIdx.y, 128-row tile = blockIdx.x). Logical row u in [0, 2*(L-r)):
// b = u>=L-r, t = u-b*(L-r). Q row = xn[b,r+t] @ u_q[L-1-r], K row = xn[b,t] @ u_k[r].
// KC=32, double-buffered, 110 KB smem -> 2 CTAs/SM. W fp32 prefetched to regs before
// the MMA section (latency hidden), converted to split-bf16 + stored after MMA.
#define MT 128
#define KC 32
#define ASTRIDE 80   // 64B row + 16B pad: 16B-aligned stride, conflict-free ldmatrix
#define A_ARR 10240  // 128*80
#define A_BUF 40960  // 4 arrays (QH,QL,KH,KL)
#define W_ARR 3840   // 48*80
#define W_BUF 15360  // 4 arrays
#define W_BASE 81920 // 2*A_BUF
#define SM_TOTAL (W_BASE + 2 * W_BUF)  // 112640 bytes

#define AQH 0
#define AQL 10240
#define AKH 20480
#define AKL 30720
#define WQH 0
#define WQL 3840
#define WKH 7680
#define WKL 11520

__device__ __forceinline__ void stage_A(uint32_t abase, int m0, int nbr, int tot, int r, int k0,
                                        int tid) {
    const char* xh = (const char*)g_xh;
    const char* xl = (const char*)g_xl;
#pragma unroll
    for (int q = tid; q < 512; q += 256) {
        const int m = q >> 2, seg = q & 3;
        const int u = m0 + m;
        const int valid = (u < tot) ? 16 : 0;
        int b = (u >= nbr) ? 1 : 0;
        int t = u - b * nbr;
        if (!valid) {
            b = 0;
            t = 0;
        }
        const int rowq = b * LL + r + t;
        const int rowk = b * LL + t;
        const size_t boff = (size_t)k0 * 2 + seg * 16;
        const uint32_t so = abase + m * ASTRIDE + seg * 16;
        cp16(so + AQH, xh + (size_t)rowq * (DD * 2) + boff, valid);
        cp16(so + AQL, xl + (size_t)rowq * (DD * 2) + boff, valid);
        cp16(so + AKH, xh + (size_t)rowk * (DD * 2) + boff, valid);
        cp16(so + AKL, xl + (size_t)rowk * (DD * 2) + boff, valid);
    }
}

// W prefetch: 3 tasks/thread, each task = (n, k2) pair; loads 2 consecutive-k fp32 for Q and K.
__device__ __forceinline__ void loadW(const float* __restrict__ Wq, const float* __restrict__ Wk,
                                      int n0, int k0, int tid, float* wq0, float* wq1, float* wk0,
                                      float* wk1) {
#pragma unroll
    for (int s = 0; s < 3; ++s) {
        const int idx = tid + s * 256;  // < 768
        const int k2 = idx / 48;
        const int n = idx - k2 * 48;
        const size_t g0 = (size_t)(k0 + 2 * k2) * NN + n0 + n;
        wq0[s] = Wq[g0];
        wq1[s] = Wq[g0 + NN];
        wk0[s] = Wk[g0];
        wk1[s] = Wk[g0 + NN];
    }
}

__device__ __forceinline__ void storeW(char* smem, uint32_t wrel, int tid, const float* wq0,
                                       const float* wq1, const float* wk0, const float* wk1) {
#pragma unroll
    for (int s = 0; s < 3; ++s) {
        const int idx = tid + s * 256;
        const int k2 = idx / 48;
        const int n = idx - k2 * 48;
        __nv_bfloat162 qh, ql, kh, kl;
        qh.x = __float2bfloat16(wq0[s]);
        qh.y = __float2bfloat16(wq1[s]);
        ql.x = __float2bfloat16(wq0[s] - __bfloat162float(qh.x));
        ql.y = __float2bfloat16(wq1[s] - __bfloat162float(qh.y));
        kh.x = __float2bfloat16(wk0[s]);
        kh.y = __float2bfloat16(wk1[s]);
        kl.x = __float2bfloat16(wk0[s] - __bfloat162float(kh.x));
        kl.y = __float2bfloat16(wk1[s] - __bfloat162float(kh.y));
        const uint32_t so = wrel + n * ASTRIDE + k2 * 4;
        *(uint32_t*)(smem + so + WQH) = *(uint32_t*)&qh;
        *(uint32_t*)(smem + so + WQL) = *(uint32_t*)&ql;
        *(uint32_t*)(smem + so + WKH) = *(uint32_t*)&kh;
        *(uint32_t*)(smem + so + WKL) = *(uint32_t*)&kl;
    }
}

__global__ void __launch_bounds__(256, 2) dots_mma_kernel(const float* __restrict__ uq,
                                                          const float* __restrict__ uk) {
    const int r = blockIdx.y;
    const int m0 = blockIdx.x * MT;
    const int nbr = LL - r;
    const int tot = 2 * nbr;
    if (m0 >= tot) return;

    extern __shared__ char smem[];
    const uint32_t sb = smem_u32(smem);
    const int tid = threadIdx.x;
    const int wid = tid >> 5, lane = tid & 31;

    const float* __restrict__ Wq = uq + (size_t)(LL - 1 - r) * DD * NN;
    const float* __restrict__ Wk = uk + (size_t)r * DD * NN;

    // prologue: stage it=0 into buffer 0
    stage_A(sb, m0, nbr, tot, r, 0, tid);
    {
        float q0[3], q1[3], k0v[3], k1v[3];
        loadW(Wq, Wk, 0, 0, tid, q0, q1, k0v, k1v);
        storeW(smem, W_BASE, tid, q0, q1, k0v, k1v);
    }
    cp_wait_all();
    __syncthreads();

    const float scale = 0.14433756729740643f; // 48^-0.5
    const int wm0 = wid * 16;
    const int a_row = wm0 + (lane & 15);
    const int a_cadd = ((lane >> 4) << 3);
    const int b_radd = ((lane >> 4) & 1) * 8 + (lane & 7);
    const int b_cadd = ((lane >> 3) & 1) * 8;

    float accQ[6][4], accK[6][4];
    int h = 0, kc = 0;
    for (int it = 0; it < 96; ++it) {
        const int buf = it & 1;
        const uint32_t aB = sb + buf * A_BUF;
        const uint32_t wB = sb + W_BASE + buf * W_BUF;
        const int nit = it + 1;
        const int nbuf = nit & 1;
        int nh = h, nkc = kc + 1;
        if (nkc == 12) {
            nkc = 0;
            nh = h + 1;
        }

        if (kc == 0) {
#pragma unroll
            for (int i = 0; i < 6; ++i)
#pragma unroll
                for (int j = 0; j < 4; ++j) {
                    accQ[i][j] = 0.f;
                    accK[i][j] = 0.f;
                }
        }

        // issue next-iteration loads (cp.async for A, LDG-to-regs for W) BEFORE MMA
        float pq0[3], pq1[3], pk0[3], pk1[3];
        if (nit < 96) {
            stage_A(sb + nbuf * A_BUF, m0, nbr, tot, r, nkc * KC, tid);
            loadW(Wq, Wk, nh * DHH, nkc * KC, tid, pq0, pq1, pk0, pk1);
        }

        // ---- MMA on current buffer ----
#pragma unroll
        for (int ks = 0; ks < 2; ++ks) {
            const uint32_t aoff = aB + a_row * ASTRIDE + (ks * 16 + a_cadd) * 2;
            uint32_t qh0, qh1, qh2, qh3, ql0, ql1, ql2, ql3;
            uint32_t kh0, kh1, kh2, kh3, kl0, kl1, kl2, kl3;
            ldsm4(aoff + AQH, qh0, qh1, qh2, qh3);
            ldsm4(aoff + AQL, ql0, ql1, ql2, ql3);
            ldsm4(aoff + AKH, kh0, kh1, kh2, kh3);
            ldsm4(aoff + AKL, kl0, kl1, kl2, kl3);
#pragma unroll
            for (int ntp = 0; ntp < 3; ++ntp) {
                const uint32_t boff = wB + (ntp * 16 + b_radd) * ASTRIDE + (ks * 16 + b_cadd) * 2;
                uint32_t wq0, wq1, wq2, wq3, wl0, wl1, wl2, wl3;
                uint32_t vk0, vk1, vk2, vk3, vl0, vl1, vl2, vl3;
                ldsm4(boff + WQH, wq0, wq1, wq2, wq3);
                ldsm4(boff + WQL, wl0, wl1, wl2, wl3);
                ldsm4(boff + WKH, vk0, vk1, vk2, vk3);
                ldsm4(boff + WKL, vl0, vl1, vl2, vl3);
                mma_bf16(accQ[2 * ntp], qh0, qh1, qh2, qh3, wq0, wq1);
                mma_bf16(accQ[2 * ntp], qh0, qh1, qh2, qh3, wl0, wl1);
                mma_bf16(accQ[2 * ntp], ql0, ql1, ql2, ql3, wq0, wq1);
                mma_bf16(accQ[2 * ntp + 1], qh0, qh1, qh2, qh3, wq2, wq3);
                mma_bf16(accQ[2 * ntp + 1], qh0, qh1, qh2, qh3, wl2, wl3);
                mma_bf16(accQ[2 * ntp + 1], ql0, ql1, ql2, ql3, wq2, wq3);
                mma_bf16(accK[2 * ntp], kh0, kh1, kh2, kh3, vk0, vk1);
                mma_bf16(accK[2 * ntp], kh0, kh1, kh2, kh3, vl0, vl1);
                mma_bf16(accK[2 * ntp], kl0, kl1, kl2, kl3, vk0, vk1);
                mma_bf16(accK[2 * ntp + 1], kh0, kh1, kh2, kh3, vk2, vk3);
                mma_bf16(accK[2 * ntp + 1], kh0, kh1, kh2, kh3, vl2, vl3);
                mma_bf16(accK[2 * ntp + 1], kl0, kl1, kl2, kl3, vk2, vk3);
            }
        }

        // ---- epilogue at end of head: diagonal pairing + row sums ----
        if (kc == 11) {
            float sl = 0.f, sh2 = 0.f;
#pragma unroll
            for (int nt = 0; nt < 6; ++nt) {
                sl += accQ[nt][0] * accK[nt][0] + accQ[nt][1] * accK[nt][1];
                sh2 += accQ[nt][2] * accK[nt][2] + accQ[nt][3] * accK[nt][3];
            }
            sl += __shfl_xor_sync(0xffffffffu, sl, 1);
            sl += __shfl_xor_sync(0xffffffffu, sl, 2);
            sh2 += __shfl_xor_sync(0xffffffffu, sh2, 1);
            sh2 += __shfl_xor_sync(0xffffffffu, sh2, 2);
            if ((lane & 3) == 0) {
                const int ur = m0 + wm0 + (lane >> 2);
#pragma unroll
                for (int half = 0; half < 2; ++half) {
                    const int u = ur + half * 8;
                    const float s = half ? sh2 : sl;
                    if (u < tot) {
                        const int b = (u >= nbr);
                        const int t = u - b * nbr;
                        const int ig = r + t;
                        g_dots[(((size_t)b * HH + h) * LL + ig) * LL + t] = s * scale;
                    }
                }
            }
        }

        // convert + store prefetched W into next buffer (after MMA; LDG latency was hidden)
        if (nit < 96) {
            storeW(smem, W_BASE + nbuf * W_BUF, tid, pq0, pq1, pk0, pk1);
        }

        cp_wait_all();
        __syncthreads();
        h = nh;
        kc = nkc;
    }
}

// ======================= causal softmax =======================
__global__ void __launch_bounds__(128) softmax_kernel() {
    const int row = blockIdx.x * 4 + (threadIdx.x >> 5);
    if (row >= BB * HH * LL) return;
    const int lane = threadIdx.x & 31;
    const int i = row % LL;
    float* d = g_dots + (size_t)row * LL;
    const int n = i + 1;
    float mx = -1e30f;
    for (int j = lane; j < n; j += 32) mx = fmaxf(mx, d[j]);
    for (int o = 16; o; o >>= 1) mx = fmaxf(mx, __shfl_xor_sync(0xffffffffu, mx, o));
    float s = 0.f;
    for (int j = lane; j < n; j += 32) {
        float e = __expf(d[j] - mx);
        d[j] = e;
        s += e;
    }
    for (int o = 16; o; o >>= 1) s += __shfl_xor_sync(0xffffffffu, s, o);
    const float inv = 1.f / s;
    for (int j = lane; j < n; j += 32) d[j] *= inv;
}

// ======================= attn @ v =======================
__global__ void __launch_bounds__(192) av_kernel() {
    const int local = threadIdx.x / DHH;
    const int dd = threadIdx.x % DHH;
    const int task = blockIdx.x * 4 + local;
    if (task >= BB * HH * LL) return;
    const int i = task % LL;
    const int bh = task / LL;
    const int h = bh % HH;
    const int b = bh / HH;
    const float* attn = g_dots + (size_t)task * LL;
    const float* vp = g_v + (size_t)b * LL * NN + h * DHH + dd;
    float acc = 0.f;
    for (int j = 0; j <= i; ++j) acc += attn[j] * vp[(size_t)j * NN];
    g_ao[((size_t)b * LL + i) * NN + h * DHH + dd] = acc;
}

// ======================= launcher =======================
extern "C" void kernel_launch(void* const* d_in, const int* in_sizes, int n_in,
                              void* d_out, int out_size) {
    const float* x = (const float*)d_in[0];
    const float* gamma = (const float*)d_in[1];
    const float* beta = (const float*)d_in[2];
    const float* uq = (const float*)d_in[3];
    const float* uk = (const float*)d_in[4];
    const float* wv = (const float*)d_in[5];
    const float* wo = (const float*)d_in[6];
    const float* bo = (const float*)d_in[7];
    float* out = (float*)d_out;

    float* g_xn_p;
    float* g_v_p;
    float* g_ao_p;
    cudaGetSymbolAddress((void**)&g_xn_p, g_xn);
    cudaGetSymbolAddress((void**)&g_v_p, g_v);
    cudaGetSymbolAddress((void**)&g_ao_p, g_ao);
    cudaFuncSetAttribute(dots_mma_kernel, cudaFuncAttributeMaxDynamicSharedMemorySize, SM_TOTAL);

    ln_kernel<<<BB * LL, 128>>>(x, gamma, beta);
    gemm32_kernel<<<dim3(12, 12), 128>>>(g_xn_p, wv, nullptr, g_v_p, 0);
    dots_mma_kernel<<<dim3(3, LL), 256, SM_TOTAL>>>(uq, uk);
    softmax_kernel<<<(BB * HH * LL + 3) / 4, 128>>>();
    av_kernel<<<(BB * HH * LL + 3) / 4, 192>>>();
    gemm32_kernel<<<dim3(12, 12), 128>>>(g_ao_p, wo, bo, out, 1);
}

// round 13
// speedup vs baseline: 1.8071x; 1.2725x over previous
#include <cuda_runtime.h>
#include <cuda_fp16.h>
#include <stdint.h>
#include <math.h>

#define BB 2
#define LL 192
#define DD 384
#define HH 8
#define DHH 48
#define NN 384
#define EPSF 1e-5f

// Scratch (allocation-free rule: __device__ globals)
__device__ float g_xn[BB * LL * DD];   // layernormed x (fp32, for v-proj)
__device__ __half g_xh[BB * LL * DD];  // xn split-fp16 hi
__device__ __half g_xl[BB * LL * DD];  // xn split-fp16 lo
__device__ float g_v[BB * LL * NN];    // v projection
__device__ float g_dots[BB * HH * LL * LL];  // attention logits -> probs (in place)
__device__ float g_ao[BB * LL * NN];         // attn @ v, head-merged

// ======================= baseline-PTX tensor helpers (sm_80+) =======================
__device__ __forceinline__ uint32_t smem_u32(const void* p) {
    uint32_t a;
    asm("{ .reg .u64 t; cvta.to.shared.u64 t, %1; cvt.u32.u64 %0, t; }" : "=r"(a) : "l"(p));
    return a;
}
__device__ __forceinline__ void ldsm4(uint32_t addr, uint32_t& r0, uint32_t& r1, uint32_t& r2,
                                      uint32_t& r3) {
    asm volatile("ldmatrix.sync.aligned.m8n8.x4.shared.b16 {%0,%1,%2,%3}, [%4];"
                 : "=r"(r0), "=r"(r1), "=r"(r2), "=r"(r3)
                 : "r"(addr));
}
__device__ __forceinline__ void mma_f16(float* c, uint32_t a0, uint32_t a1, uint32_t a2,
                                        uint32_t a3, uint32_t b0, uint32_t b1) {
    asm volatile(
        "mma.sync.aligned.m16n8k16.row.col.f32.f16.f16.f32 "
        "{%0,%1,%2,%3}, {%4,%5,%6,%7}, {%8,%9}, {%0,%1,%2,%3};"
        : "+f"(c[0]), "+f"(c[1]), "+f"(c[2]), "+f"(c[3])
        : "r"(a0), "r"(a1), "r"(a2), "r"(a3), "r"(b0), "r"(b1));
}
__device__ __forceinline__ void cp16(uint32_t dst, const void* src, int src_bytes) {
    asm volatile("cp.async.cg.shared.global [%0], [%1], 16, %2;" ::"r"(dst), "l"(src),
                 "r"(src_bytes)
                 : "memory");
}
__device__ __forceinline__ void cp_wait_all() {
    asm volatile("cp.async.wait_all;" ::: "memory");
}

// ======================= LayerNorm (+ split-fp16 precompute) =======================
__global__ void __launch_bounds__(128) ln_kernel(const float* __restrict__ x,
                                                 const float* __restrict__ gamma,
                                                 const float* __restrict__ beta) {
    const int row = blockIdx.x;
    const int tid = threadIdx.x;
    const float* xr = x + (size_t)row * DD;
    float s = 0.f, s2 = 0.f;
    for (int c = tid; c < DD; c += 128) {
        float t = xr[c];
        s += t;
        s2 += t * t;
    }
    for (int o = 16; o; o >>= 1) {
        s += __shfl_xor_sync(0xffffffffu, s, o);
        s2 += __shfl_xor_sync(0xffffffffu, s2, o);
    }
    __shared__ float sh[8];
    const int w = tid >> 5;
    if ((tid & 31) == 0) {
        sh[w] = s;
        sh[4 + w] = s2;
    }
    __syncthreads();
    s = sh[0] + sh[1] + sh[2] + sh[3];
    s2 = sh[4] + sh[5] + sh[6] + sh[7];
    const float mu = s * (1.0f / DD);
    const float var = s2 * (1.0f / DD) - mu * mu;
    const float rstd = rsqrtf(var + EPSF);
    for (int c = tid; c < DD; c += 128) {
        const float v = (xr[c] - mu) * rstd * gamma[c] + beta[c];
        g_xn[(size_t)row * DD + c] = v;
        const __half hi = __float2half_rn(v);
        g_xh[(size_t)row * DD + c] = hi;
        g_xl[(size_t)row * DD + c] = __float2half_rn(v - __half2float(hi));
    }
}

// ======================= small fp32 GEMM, 32x32 tiles (v / o projections) =======================
__global__ void __launch_bounds__(128) gemm32_kernel(const float* __restrict__ A,
                                                     const float* __restrict__ Bw,
                                                     const float* __restrict__ bias,
                                                     float* __restrict__ C, int has_bias) {
    __shared__ float As[32][33];
    __shared__ float Bs[32][36];
    const int bm = blockIdx.y * 32, bn = blockIdx.x * 32;
    const int tid = threadIdx.x;
    const int tx = tid & 7, ty = tid >> 3;  // 8 x 4 cols, 16 x 2 rows
    float acc[2][4] = {};
    for (int k0 = 0; k0 < 384; k0 += 32) {
#pragma unroll
        for (int idx = tid; idx < 1024; idx += 128) {
            const int m = idx >> 5, kk = idx & 31;
            As[kk][m] = A[(size_t)(bm + m) * 384 + k0 + kk];
        }
#pragma unroll
        for (int idx = tid; idx < 1024; idx += 128) {
            const int kk = idx >> 5, n = idx & 31;
            Bs[kk][n] = Bw[(size_t)(k0 + kk) * 384 + bn + n];
        }
        __syncthreads();
#pragma unroll
        for (int kk = 0; kk < 32; ++kk) {
            const float a0 = As[kk][ty * 2], a1 = As[kk][ty * 2 + 1];
            const float4 b4 = *(const float4*)&Bs[kk][tx * 4];
            const float b[4] = {b4.x, b4.y, b4.z, b4.w};
#pragma unroll
            for (int j = 0; j < 4; ++j) {
                acc[0][j] += a0 * b[j];
                acc[1][j] += a1 * b[j];
            }
        }
        __syncthreads();
    }
#pragma unroll
    for (int i = 0; i < 2; ++i)
#pragma unroll
        for (int j = 0; j < 4; ++j) {
            const int row = bm + ty * 2 + i, col = bn + tx * 4 + j;
            float o = acc[i][j];
            if (has_bias) o += bias[col];
            C[(size_t)row * 384 + col] = o;
        }
}

// ======================= dots via mma.sync HMMA (split-fp16 A, fp16 W, 2 products) ==========
// CTA = (r = blockIdx.y, 128-row tile = blockIdx.x). Logical row u in [0, 2*(L-r)):
// b = u>=L-r, t = u-b*(L-r). Q row = xn[b,r+t] @ u_q[L-1-r], K row = xn[b,t] @ u_k[r].
// Q = (xh+xl) @ wh : x is exact to ~2^-22, only W carries fp16 rounding (~1e-4 dot rms).
#define MT 128
#define KC 32
#define ASTRIDE 80   // 64B row + 16B pad: 16B-aligned stride, conflict-free ldmatrix
#define A_ARR 10240  // 128*80
#define A_BUF 40960  // 4 arrays (QH,QL,KH,KL)
#define W_ARR 3840   // 48*80
#define W_BUF 7680   // 2 arrays (WQH, WKH)
#define W_BASE 81920  // 2*A_BUF
#define SM_TOTAL (W_BASE + 2 * W_BUF)  // 97280 bytes

#define AQH 0
#define AQL 10240
#define AKH 20480
#define AKL 30720
#define WQH 0
#define WKH 3840

__device__ __forceinline__ void stage_A(uint32_t abase, int m0, int nbr, int tot, int r, int k0,
                                        int tid) {
    const char* xh = (const char*)g_xh;
    const char* xl = (const char*)g_xl;
#pragma unroll
    for (int q = tid; q < 512; q += 256) {
        const int m = q >> 2, seg = q & 3;
        const int u = m0 + m;
        const int valid = (u < tot) ? 16 : 0;
        int b = (u >= nbr) ? 1 : 0;
        int t = u - b * nbr;
        if (!valid) {
            b = 0;
            t = 0;
        }
        const int rowq = b * LL + r + t;
        const int rowk = b * LL + t;
        const size_t boff = (size_t)k0 * 2 + seg * 16;
        const uint32_t so = abase + m * ASTRIDE + seg * 16;
        cp16(so + AQH, xh + (size_t)rowq * (DD * 2) + boff, valid);
        cp16(so + AQL, xl + (size_t)rowq * (DD * 2) + boff, valid);
        cp16(so + AKH, xh + (size_t)rowk * (DD * 2) + boff, valid);
        cp16(so + AKL, xl + (size_t)rowk * (DD * 2) + boff, valid);
    }
}

// W prefetch: 3 tasks/thread, each task = (n, k2) pair; loads 2 consecutive-k fp32 for Q and K.
__device__ __forceinline__ void loadW(const float* __restrict__ Wq, const float* __restrict__ Wk,
                                      int n0, int k0, int tid, float* wq0, float* wq1, float* wk0,
                                      float* wk1) {
#pragma unroll
    for (int s = 0; s < 3; ++s) {
        const int idx = tid + s * 256;  // < 768
        const int k2 = idx / 48;
        const int n = idx - k2 * 48;
        const size_t g0 = (size_t)(k0 + 2 * k2) * NN + n0 + n;
        wq0[s] = Wq[g0];
        wq1[s] = Wq[g0 + NN];
        wk0[s] = Wk[g0];
        wk1[s] = Wk[g0 + NN];
    }
}

__device__ __forceinline__ void storeW(char* smem, uint32_t wrel, int tid, const float* wq0,
                                       const float* wq1, const float* wk0, const float* wk1) {
#pragma unroll
    for (int s = 0; s < 3; ++s) {
        const int idx = tid + s * 256;
        const int k2 = idx / 48;
        const int n = idx - k2 * 48;
        __half2 qh, kh;
        qh.x = __float2half_rn(wq0[s]);
        qh.y = __float2half_rn(wq1[s]);
        kh.x = __float2half_rn(wk0[s]);
        kh.y = __float2half_rn(wk1[s]);
        const uint32_t so = wrel + n * ASTRIDE + k2 * 4;
        *(uint32_t*)(smem + so + WQH) = *(uint32_t*)&qh;
        *(uint32_t*)(smem + so + WKH) = *(uint32_t*)&kh;
    }
}

__global__ void __launch_bounds__(256, 2) dots_mma_kernel(const float* __restrict__ uq,
                                                          const float* __restrict__ uk) {
    const int r = blockIdx.y;
    const int m0 = blockIdx.x * MT;
    const int nbr = LL - r;
    const int tot = 2 * nbr;
    if (m0 >= tot) return;

    extern __shared__ char smem[];
    const uint32_t sb = smem_u32(smem);
    const int tid = threadIdx.x;
    const int wid = tid >> 5, lane = tid & 31;

    const float* __restrict__ Wq = uq + (size_t)(LL - 1 - r) * DD * NN;
    const float* __restrict__ Wk = uk + (size_t)r * DD * NN;

    // prologue: stage it=0 into buffer 0
    stage_A(sb, m0, nbr, tot, r, 0, tid);
    {
        float q0[3], q1[3], k0v[3], k1v[3];
        loadW(Wq, Wk, 0, 0, tid, q0, q1, k0v, k1v);
        storeW(smem, W_BASE, tid, q0, q1, k0v, k1v);
    }
    cp_wait_all();
    __syncthreads();

    const float scale = 0.14433756729740643f;  // 48^-0.5
    const int wm0 = wid * 16;
    const int a_row = wm0 + (lane & 15);
    const int a_cadd = ((lane >> 4) << 3);
    const int b_radd = ((lane >> 4) & 1) * 8 + (lane & 7);
    const int b_cadd = ((lane >> 3) & 1) * 8;

    float accQ[6][4], accK[6][4];
    int h = 0, kc = 0;
    for (int it = 0; it < 96; ++it) {
        const int buf = it & 1;
        const uint32_t aB = sb + buf * A_BUF;
        const uint32_t wB = sb + W_BASE + buf * W_BUF;
        const int nit = it + 1;
        const int nbuf = nit & 1;
        int nh = h, nkc = kc + 1;
        if (nkc == 12) {
            nkc = 0;
            nh = h + 1;
        }

        if (kc == 0) {
#pragma unroll
            for (int i = 0; i < 6; ++i)
#pragma unroll
                for (int j = 0; j < 4; ++j) {
                    accQ[i][j] = 0.f;
                    accK[i][j] = 0.f;
                }
        }

        // issue next-iteration loads (cp.async for A, LDG-to-regs for W) BEFORE MMA
        float pq0[3], pq1[3], pk0[3], pk1[3];
        if (nit < 96) {
            stage_A(sb + nbuf * A_BUF, m0, nbr, tot, r, nkc * KC, tid);
            loadW(Wq, Wk, nh * DHH, nkc * KC, tid, pq0, pq1, pk0, pk1);
        }

        // ---- MMA on current buffer ----
#pragma unroll
        for (int ks = 0; ks < 2; ++ks) {
            const uint32_t aoff = aB + a_row * ASTRIDE + (ks * 16 + a_cadd) * 2;
            uint32_t qh0, qh1, qh2, qh3, ql0, ql1, ql2, ql3;
            uint32_t kh0, kh1, kh2, kh3, kl0, kl1, kl2, kl3;
            ldsm4(aoff + AQH, qh0, qh1, qh2, qh3);
            ldsm4(aoff + AQL, ql0, ql1, ql2, ql3);
            ldsm4(aoff + AKH, kh0, kh1, kh2, kh3);
            ldsm4(aoff + AKL, kl0, kl1, kl2, kl3);
#pragma unroll
            for (int ntp = 0; ntp < 3; ++ntp) {
                const uint32_t boff = wB + (ntp * 16 + b_radd) * ASTRIDE + (ks * 16 + b_cadd) * 2;
                uint32_t wq0, wq1, wq2, wq3;
                uint32_t vk0, vk1, vk2, vk3;
                ldsm4(boff + WQH, wq0, wq1, wq2, wq3);
                ldsm4(boff + WKH, vk0, vk1, vk2, vk3);
                // Q = xh@wh + xl@wh
                mma_f16(accQ[2 * ntp], qh0, qh1, qh2, qh3, wq0, wq1);
                mma_f16(accQ[2 * ntp], ql0, ql1, ql2, ql3, wq0, wq1);
                mma_f16(accQ[2 * ntp + 1], qh0, qh1, qh2, qh3, wq2, wq3);
                mma_f16(accQ[2 * ntp + 1], ql0, ql1, ql2, ql3, wq2, wq3);
                // K
                mma_f16(accK[2 * ntp], kh0, kh1, kh2, kh3, vk0, vk1);
                mma_f16(accK[2 * ntp], kl0, kl1, kl2, kl3, vk0, vk1);
                mma_f16(accK[2 * ntp + 1], kh0, kh1, kh2, kh3, vk2, vk3);
                mma_f16(accK[2 * ntp + 1], kl0, kl1, kl2, kl3, vk2, vk3);
            }
        }

        // ---- epilogue at end of head: diagonal pairing + row sums ----
        if (kc == 11) {
            float sl = 0.f, sh2 = 0.f;
#pragma unroll
            for (int nt = 0; nt < 6; ++nt) {
                sl += accQ[nt][0] * accK[nt][0] + accQ[nt][1] * accK[nt][1];
                sh2 += accQ[nt][2] * accK[nt][2] + accQ[nt][3] * accK[nt][3];
            }
            sl += __shfl_xor_sync(0xffffffffu, sl, 1);
            sl += __shfl_xor_sync(0xffffffffu, sl, 2);
            sh2 += __shfl_xor_sync(0xffffffffu, sh2, 1);
            sh2 += __shfl_xor_sync(0xffffffffu, sh2, 2);
            if ((lane & 3) == 0) {
                const int ur = m0 + wm0 + (lane >> 2);
#pragma unroll
                for (int half = 0; half < 2; ++half) {
                    const int u = ur + half * 8;
                    const float s = half ? sh2 : sl;
                    if (u < tot) {
                        const int b = (u >= nbr);
                        const int t = u - b * nbr;
                        const int ig = r + t;
                        g_dots[(((size_t)b * HH + h) * LL + ig) * LL + t] = s * scale;
                    }
                }
            }
        }

        // convert + store prefetched W into next buffer (after MMA; LDG latency was hidden)
        if (nit < 96) {
            storeW(smem, W_BASE + nbuf * W_BUF, tid, pq0, pq1, pk0, pk1);
        }

        cp_wait_all();
        __syncthreads();
        h = nh;
        kc = nkc;
    }
}

// ======================= causal softmax =======================
__global__ void __launch_bounds__(128) softmax_kernel() {
    const int row = blockIdx.x * 4 + (threadIdx.x >> 5);
    if (row >= BB * HH * LL) return;
    const int lane = threadIdx.x & 31;
    const int i = row % LL;
    float* d = g_dots + (size_t)row * LL;
    const int n = i + 1;
    float mx = -1e30f;
    for (int j = lane; j < n; j += 32) mx = fmaxf(mx, d[j]);
    for (int o = 16; o; o >>= 1) mx = fmaxf(mx, __shfl_xor_sync(0xffffffffu, mx, o));
    float s = 0.f;
    for (int j = lane; j < n; j += 32) {
        float e = __expf(d[j] - mx);
        d[j] = e;
        s += e;
    }
    for (int o = 16; o; o >>= 1) s += __shfl_xor_sync(0xffffffffu, s, o);
    const float inv = 1.f / s;
    for (int j = lane; j < n; j += 32) d[j] *= inv;
}

// ======================= attn @ v =======================
__global__ void __launch_bounds__(192) av_kernel() {
    const int local = threadIdx.x / DHH;
    const int dd = threadIdx.x % DHH;
    const int task = blockIdx.x * 4 + local;
    if (task >= BB * HH * LL) return;
    const int i = task % LL;
    const int bh = task / LL;
    const int h = bh % HH;
    const int b = bh / HH;
    const float* attn = g_dots + (size_t)task * LL;
    const float* vp = g_v + (size_t)b * LL * NN + h * DHH + dd;
    float acc = 0.f;
    for (int j = 0; j <= i; ++j) acc += attn[j] * vp[(size_t)j * NN];
    g_ao[((size_t)b * LL + i) * NN + h * DHH + dd] = acc;
}

// ======================= launcher =======================
extern "C" void kernel_launch(void* const* d_in, const int* in_sizes, int n_in,
                              void* d_out, int out_size) {
    const float* x = (const float*)d_in[0];
    const float* gamma = (const float*)d_in[1];
    const float* beta = (const float*)d_in[2];
    const float* uq = (const float*)d_in[3];
    const float* uk = (const float*)d_in[4];
    const float* wv = (const float*)d_in[5];
    const float* wo = (const float*)d_in[6];
    const float* bo = (const float*)d_in[7];
    float* out = (float*)d_out;

    float* g_xn_p;
    float* g_v_p;
    float* g_ao_p;
    cudaGetSymbolAddress((void**)&g_xn_p, g_xn);
    cudaGetSymbolAddress((void**)&g_v_p, g_v);
    cudaGetSymbolAddress((void**)&g_ao_p, g_ao);
    cudaFuncSetAttribute(dots_mma_kernel, cudaFuncAttributeMaxDynamicSharedMemorySize, SM_TOTAL);

    ln_kernel<<<BB * LL, 128>>>(x, gamma, beta);
    gemm32_kernel<<<dim3(12, 12), 128>>>(g_xn_p, wv, nullptr, g_v_p, 0);
    dots_mma_kernel<<<dim3(3, LL), 256, SM_TOTAL>>>(uq, uk);
    softmax_kernel<<<(BB * HH * LL + 3) / 4, 128>>>();
    av_kernel<<<(BB * HH * LL + 3) / 4, 192>>>();
    gemm32_kernel<<<dim3(12, 12), 128>>>(g_ao_p, wo, bo, out, 1);
}